// round 3
// baseline (speedup 1.0000x reference)
#include <cuda_runtime.h>
#include <cuda_bf16.h>

// Causal depthwise conv1d (K=4) + SiLU over x:(B,S,D) fp32, channel-innermost.
// y[b,s,d] = silu( sum_{k=0..3} w[d,0,k] * x[b, s-3+k, d] )  (zero-pad s<0)
//
// Strategy: thread owns 4 consecutive channels (float4), walks CHUNK steps of s
// carrying the 3-deep history in registers. Every x element read exactly once.
// Pure HBM-bound streaming kernel: 256MB in + 256MB out.

#define TPB   128
#define CHUNK 64

__global__ __launch_bounds__(TPB)
void causal_conv1d_silu_kernel(const float4* __restrict__ x,
                               const float4* __restrict__ w,   // (D,1,K) fp32 -> per-channel float4 of taps
                               float4* __restrict__ y,
                               int S, int D4)
{
    const int d4 = blockIdx.x * TPB + threadIdx.x;   // float4-channel index
    const int s0 = blockIdx.y * CHUNK;
    const int b  = blockIdx.z;

    // Per-channel taps: channel c = 4*d4 + c has taps w[4*d4 + c] (contiguous K=4 floats).
    const float4 w0 = w[4 * d4 + 0];
    const float4 w1 = w[4 * d4 + 1];
    const float4 w2 = w[4 * d4 + 2];
    const float4 w3 = w[4 * d4 + 3];

    size_t base = ((size_t)b * S + s0) * (size_t)D4 + (size_t)d4;

    // History registers: p1 = x[s0-1], p2 = x[s0-2], p3 = x[s0-3]
    const float4 z = make_float4(0.f, 0.f, 0.f, 0.f);
    float4 p1, p2, p3;
    if (s0 >= 3) {
        p1 = x[base - 1 * (size_t)D4];
        p2 = x[base - 2 * (size_t)D4];
        p3 = x[base - 3 * (size_t)D4];
    } else {
        p1 = (s0 >= 1) ? x[base - 1 * (size_t)D4] : z;
        p2 = (s0 >= 2) ? x[base - 2 * (size_t)D4] : z;
        p3 = z;
    }

    #pragma unroll 8
    for (int i = 0; i < CHUNK; ++i) {
        const float4 cur = x[base + (size_t)i * (size_t)D4];

        float4 r;
        // tap order: k=0 -> x[s-3] (oldest), k=3 -> x[s] (current)
        r.x = w0.x * p3.x + w0.y * p2.x + w0.z * p1.x + w0.w * cur.x;
        r.y = w1.x * p3.y + w1.y * p2.y + w1.z * p1.y + w1.w * cur.y;
        r.z = w2.x * p3.z + w2.y * p2.z + w2.z * p1.z + w2.w * cur.z;
        r.w = w3.x * p3.w + w3.y * p2.w + w3.z * p1.w + w3.w * cur.w;

        // SiLU: v * sigmoid(v)
        r.x = r.x / (1.0f + __expf(-r.x));
        r.y = r.y / (1.0f + __expf(-r.y));
        r.z = r.z / (1.0f + __expf(-r.z));
        r.w = r.w / (1.0f + __expf(-r.w));

        y[base + (size_t)i * (size_t)D4] = r;

        p3 = p2; p2 = p1; p1 = cur;
    }
}

extern "C" void kernel_launch(void* const* d_in, const int* in_sizes, int n_in,
                              void* d_out, int out_size)
{
    const float* x = (const float*)d_in[0];
    const float* w = (const float*)d_in[1];
    float*       y = (float*)d_out;

    const int K = 4;
    const int D = in_sizes[1] / K;          // w has D*1*K elements -> D = 2048
    const int S = 8192;
    const int B = in_sizes[0] / (S * D);    // 4

    const int D4 = D / 4;                   // 512 float4 channel-groups

    dim3 block(TPB);
    dim3 grid(D4 / TPB, S / CHUNK, B);      // (4, 128, 4) = 2048 blocks

    causal_conv1d_silu_kernel<<<grid, block>>>(
        (const float4*)x, (const float4*)w, (float4*)y, S, D4);
}

// round 4
// speedup vs baseline: 1.3929x; 1.3929x over previous
#include <cuda_runtime.h>
#include <cuda_bf16.h>

// Causal depthwise conv1d (K=4) + SiLU over x:(B,S,D) fp32, channel-innermost.
// y[b,s,d] = silu( sum_{k=0..3} w[d,0,k] * x[b, s-3+k, d] )  (zero left-pad)
//
// R3: HBM-bound streaming kernel.
//  - thread owns 4 consecutive channels (float4), walks CHUNK s-steps with
//    register-carried 3-deep history (each x element read ~once + 9% halo)
//  - explicit GROUP=8 load batch -> guaranteed MLP_p1=8
//  - __fdividef instead of full-precision div (was ~8 FFMA + MUFU each)
//  - CHUNK=32 -> 4096 blocks -> ~3.3 waves (was 1.54: half-empty 2nd wave)
//  - __stcs on output (never re-read) to preserve L2 for halo reuse

#define TPB   128
#define CHUNK 32
#define GROUP 8

__device__ __forceinline__ float silu_fast(float v) {
    return __fdividef(v, 1.0f + __expf(-v));
}

__global__ __launch_bounds__(TPB)
void causal_conv1d_silu_kernel(const float4* __restrict__ x,
                               const float4* __restrict__ w,   // (D,1,K) -> per-channel float4 taps
                               float4* __restrict__ y,
                               int S, int D4)
{
    const int d4 = blockIdx.x * TPB + threadIdx.x;   // float4-channel group index
    const int s0 = blockIdx.y * CHUNK;
    const int b  = blockIdx.z;

    const float4 w0 = w[4 * d4 + 0];
    const float4 w1 = w[4 * d4 + 1];
    const float4 w2 = w[4 * d4 + 2];
    const float4 w3 = w[4 * d4 + 3];

    const size_t base = ((size_t)b * S + s0) * (size_t)D4 + (size_t)d4;
    const size_t st   = (size_t)D4;

    // History: p1 = x[s0-1], p2 = x[s0-2], p3 = x[s0-3] (zero before s=0)
    const float4 z = make_float4(0.f, 0.f, 0.f, 0.f);
    float4 p1, p2, p3;
    if (s0 >= 3) {
        p1 = x[base - 1 * st];
        p2 = x[base - 2 * st];
        p3 = x[base - 3 * st];
    } else {
        p1 = (s0 >= 1) ? x[base - 1 * st] : z;
        p2 = (s0 >= 2) ? x[base - 2 * st] : z;
        p3 = z;
    }

    #pragma unroll
    for (int g = 0; g < CHUNK; g += GROUP) {
        // Batched loads: GROUP independent LDG.128 in flight before any compute.
        float4 c[GROUP];
        #pragma unroll
        for (int j = 0; j < GROUP; ++j)
            c[j] = x[base + (size_t)(g + j) * st];

        #pragma unroll
        for (int j = 0; j < GROUP; ++j) {
            const float4 cur = c[j];
            float4 r;
            // taps: k=0 -> x[s-3] (oldest) ... k=3 -> x[s]
            r.x = w0.x * p3.x + w0.y * p2.x + w0.z * p1.x + w0.w * cur.x;
            r.y = w1.x * p3.y + w1.y * p2.y + w1.z * p1.y + w1.w * cur.y;
            r.z = w2.x * p3.z + w2.y * p2.z + w2.z * p1.z + w2.w * cur.z;
            r.w = w3.x * p3.w + w3.y * p2.w + w3.z * p1.w + w3.w * cur.w;

            r.x = silu_fast(r.x);
            r.y = silu_fast(r.y);
            r.z = silu_fast(r.z);
            r.w = silu_fast(r.w);

            __stcs(&y[base + (size_t)(g + j) * st], r);

            p3 = p2; p2 = p1; p1 = cur;
        }
    }
}

extern "C" void kernel_launch(void* const* d_in, const int* in_sizes, int n_in,
                              void* d_out, int out_size)
{
    const float* x = (const float*)d_in[0];
    const float* w = (const float*)d_in[1];
    float*       y = (float*)d_out;

    const int K = 4;
    const int D = in_sizes[1] / K;          // 2048
    const int S = 8192;
    const int B = in_sizes[0] / (S * D);    // 4

    const int D4 = D / 4;                   // 512

    dim3 block(TPB);
    dim3 grid(D4 / TPB, S / CHUNK, B);      // (4, 256, 4) = 4096 blocks

    causal_conv1d_silu_kernel<<<grid, block>>>(
        (const float4*)x, (const float4*)w, (float4*)y, S, D4);
}

// round 5
// speedup vs baseline: 1.4110x; 1.0130x over previous
#include <cuda_runtime.h>
#include <cuda_bf16.h>

// Causal depthwise conv1d (K=4) + SiLU over x:(B,S,D) fp32, channel-innermost.
// y[b,s,d] = silu( sum_{k=0..3} w[d,0,k] * x[b, s-3+k, d] )  (zero left-pad)
//
// R4: single-wave persistent strips.
//  - grid = 4 x 92 x 4 = 1472 blocks <= 1480 (148 SMs x 10 blocks @ <=51 regs)
//    -> exactly one wave, no quantization, no inter-wave drain.
//  - each block owns a contiguous ~89-row s-strip: register-carried history,
//    halo reads only 3 rows per ~89 (3.4% vs 9.4% at CHUNK=32).
//  - GROUP=8 batched LDG.128 for MLP; __fdividef SiLU; __stcs stores.

#define TPB   128
#define NSEG  92
#define GROUP 8

__device__ __forceinline__ float silu_fast(float v) {
    return __fdividef(v, 1.0f + __expf(-v));
}

__global__ __launch_bounds__(TPB, 10)
void causal_conv1d_silu_kernel(const float4* __restrict__ x,
                               const float4* __restrict__ w,   // (D,1,K) -> per-channel float4 taps
                               float4* __restrict__ y,
                               int S, int D4)
{
    const int d4  = blockIdx.x * TPB + threadIdx.x;  // float4-channel group
    const int seg = blockIdx.y;                      // s-segment
    const int b   = blockIdx.z;

    // Balanced segment bounds: lengths differ by at most 1 row.
    const int s0 = (int)(((long long)seg       * S) / NSEG);
    const int s1 = (int)(((long long)(seg + 1) * S) / NSEG);

    const float4 w0 = w[4 * d4 + 0];
    const float4 w1 = w[4 * d4 + 1];
    const float4 w2 = w[4 * d4 + 2];
    const float4 w3 = w[4 * d4 + 3];

    const size_t st   = (size_t)D4;
    const size_t base = ((size_t)b * S + s0) * st + (size_t)d4;

    // History: p1 = x[s0-1], p2 = x[s0-2], p3 = x[s0-3] (zero before s=0).
    // seg > 0 implies s0 >= 89 >= 3.
    const float4 z = make_float4(0.f, 0.f, 0.f, 0.f);
    float4 p1 = z, p2 = z, p3 = z;
    if (s0 >= 3) {
        p1 = x[base - 1 * st];
        p2 = x[base - 2 * st];
        p3 = x[base - 3 * st];
    }

    const int n = s1 - s0;
    int i = 0;

    // Main loop: batches of GROUP independent LDG.128, then compute+store.
    for (; i + GROUP <= n; i += GROUP) {
        float4 c[GROUP];
        #pragma unroll
        for (int j = 0; j < GROUP; ++j)
            c[j] = x[base + (size_t)(i + j) * st];

        #pragma unroll
        for (int j = 0; j < GROUP; ++j) {
            const float4 cur = c[j];
            float4 r;
            r.x = w0.x * p3.x + w0.y * p2.x + w0.z * p1.x + w0.w * cur.x;
            r.y = w1.x * p3.y + w1.y * p2.y + w1.z * p1.y + w1.w * cur.y;
            r.z = w2.x * p3.z + w2.y * p2.z + w2.z * p1.z + w2.w * cur.z;
            r.w = w3.x * p3.w + w3.y * p2.w + w3.z * p1.w + w3.w * cur.w;

            r.x = silu_fast(r.x);
            r.y = silu_fast(r.y);
            r.z = silu_fast(r.z);
            r.w = silu_fast(r.w);

            __stcs(&y[base + (size_t)(i + j) * st], r);

            p3 = p2; p2 = p1; p1 = cur;
        }
    }

    // Tail (< GROUP rows).
    for (; i < n; ++i) {
        const float4 cur = x[base + (size_t)i * st];
        float4 r;
        r.x = w0.x * p3.x + w0.y * p2.x + w0.z * p1.x + w0.w * cur.x;
        r.y = w1.x * p3.y + w1.y * p2.y + w1.z * p1.y + w1.w * cur.y;
        r.z = w2.x * p3.z + w2.y * p2.z + w2.z * p1.z + w2.w * cur.z;
        r.w = w3.x * p3.w + w3.y * p2.w + w3.z * p1.w + w3.w * cur.w;

        r.x = silu_fast(r.x);
        r.y = silu_fast(r.y);
        r.z = silu_fast(r.z);
        r.w = silu_fast(r.w);

        __stcs(&y[base + (size_t)i * st], r);

        p3 = p2; p2 = p1; p1 = cur;
    }
}

extern "C" void kernel_launch(void* const* d_in, const int* in_sizes, int n_in,
                              void* d_out, int out_size)
{
    const float* x = (const float*)d_in[0];
    const float* w = (const float*)d_in[1];
    float*       y = (float*)d_out;

    const int K = 4;
    const int D = in_sizes[1] / K;          // 2048
    const int S = 8192;
    const int B = in_sizes[0] / (S * D);    // 4

    const int D4 = D / 4;                   // 512

    dim3 block(TPB);
    dim3 grid(D4 / TPB, NSEG, B);           // (4, 92, 4) = 1472 blocks (single wave)

    causal_conv1d_silu_kernel<<<grid, block>>>(
        (const float4*)x, (const float4*)w, (float4*)y, S, D4);
}

// round 6
// speedup vs baseline: 1.4454x; 1.0244x over previous
#include <cuda_runtime.h>
#include <cuda_bf16.h>

// Causal depthwise conv1d (K=4) + SiLU over x:(B,S,D) fp32, channel-innermost.
// y[b,s,d] = silu( sum_{k=0..3} w[d,0,k] * x[b, s-3+k, d] )  (zero left-pad)
//
// R5: fine-grained multi-wave tiles.
//  - CHUNK=16 -> 8192 blocks -> ~5.5 waves: HW work-steal (wave>=2) balances
//    CTA skew; tail quantization ~ half a tile (R4 single-wave exposed full
//    CTA spread as tail idle -> regressed).
//  - halo reads (3 rows per 16) hit L2: adjacent-segment blocks run nearly
//    concurrently, so DRAM traffic stays at the 512MB floor.
//  - GROUP=8 batched LDG.128 for MLP; __fdividef SiLU; __stcs stores.

#define TPB   128
#define CHUNK 16
#define GROUP 8

__device__ __forceinline__ float silu_fast(float v) {
    return __fdividef(v, 1.0f + __expf(-v));
}

__global__ __launch_bounds__(TPB)
void causal_conv1d_silu_kernel(const float4* __restrict__ x,
                               const float4* __restrict__ w,   // (D,1,K) -> per-channel float4 taps
                               float4* __restrict__ y,
                               int S, int D4)
{
    const int d4 = blockIdx.x * TPB + threadIdx.x;   // float4-channel group
    const int s0 = blockIdx.y * CHUNK;
    const int b  = blockIdx.z;

    const float4 w0 = w[4 * d4 + 0];
    const float4 w1 = w[4 * d4 + 1];
    const float4 w2 = w[4 * d4 + 2];
    const float4 w3 = w[4 * d4 + 3];

    const size_t st   = (size_t)D4;
    const size_t base = ((size_t)b * S + s0) * st + (size_t)d4;

    // History: p1 = x[s0-1], p2 = x[s0-2], p3 = x[s0-3] (zero before s=0).
    const float4 z = make_float4(0.f, 0.f, 0.f, 0.f);
    float4 p1 = z, p2 = z, p3 = z;
    if (s0 >= 3) {
        p1 = x[base - 1 * st];
        p2 = x[base - 2 * st];
        p3 = x[base - 3 * st];
    }

    #pragma unroll
    for (int g = 0; g < CHUNK; g += GROUP) {
        // Batched loads: GROUP independent LDG.128 in flight before compute.
        float4 c[GROUP];
        #pragma unroll
        for (int j = 0; j < GROUP; ++j)
            c[j] = x[base + (size_t)(g + j) * st];

        #pragma unroll
        for (int j = 0; j < GROUP; ++j) {
            const float4 cur = c[j];
            float4 r;
            // taps: k=0 -> x[s-3] (oldest) ... k=3 -> x[s]
            r.x = w0.x * p3.x + w0.y * p2.x + w0.z * p1.x + w0.w * cur.x;
            r.y = w1.x * p3.y + w1.y * p2.y + w1.z * p1.y + w1.w * cur.y;
            r.z = w2.x * p3.z + w2.y * p2.z + w2.z * p1.z + w2.w * cur.z;
            r.w = w3.x * p3.w + w3.y * p2.w + w3.z * p1.w + w3.w * cur.w;

            r.x = silu_fast(r.x);
            r.y = silu_fast(r.y);
            r.z = silu_fast(r.z);
            r.w = silu_fast(r.w);

            __stcs(&y[base + (size_t)(g + j) * st], r);

            p3 = p2; p2 = p1; p1 = cur;
        }
    }
}

extern "C" void kernel_launch(void* const* d_in, const int* in_sizes, int n_in,
                              void* d_out, int out_size)
{
    const float* x = (const float*)d_in[0];
    const float* w = (const float*)d_in[1];
    float*       y = (float*)d_out;

    const int K = 4;
    const int D = in_sizes[1] / K;          // 2048
    const int S = 8192;
    const int B = in_sizes[0] / (S * D);    // 4

    const int D4 = D / 4;                   // 512

    dim3 block(TPB);
    dim3 grid(D4 / TPB, S / CHUNK, B);      // (4, 512, 4) = 8192 blocks

    causal_conv1d_silu_kernel<<<grid, block>>>(
        (const float4*)x, (const float4*)w, (float4*)y, S, D4);
}